// round 12
// baseline (speedup 1.0000x reference)
#include <cuda_runtime.h>
#include <math.h>
#include <stdint.h>

#define BB 2
#define LL 4096
#define CC 1024
#define NHH 16
#define DHH 64
#define MM 1638
#define C3 3072
#define LSPLIT 16

// GEMM tiling: 128x128 CTA tile, 32 k-step, 256 threads, 8x8 per thread
#define GTM 128
#define GTN 128
#define GKC 32
#define APAD 132   // smem pitch in floats (16B-aligned, reduces store conflicts)

// ---------------- scratch (device globals; no allocations allowed) ----------
__device__ double g_part[LSPLIT * BB * CC];
__device__ float  g_mse[BB * LL];
__device__ int    g_idx[BB * MM];
__device__ int    g_minv[BB * LL];
__device__ float  g_bias3[C3];
__device__ float  g_scl[NHH];
__device__ float  g_qkv[(size_t)BB * MM * C3];
__device__ float  g_q[(size_t)BB * NHH * MM * DHH];
__device__ float  g_k[(size_t)BB * NHH * MM * DHH];
__device__ float  g_v[(size_t)BB * NHH * MM * DHH];
__device__ float  g_ao[(size_t)BB * MM * CC];
__device__ float  g_po[(size_t)BB * MM * CC];

// ---------------- packed f32x2 helpers ---------------------------------------
__device__ __forceinline__ void ffma2(uint64_t& acc, uint64_t a, uint64_t b) {
    asm("fma.rn.f32x2 %0, %1, %2, %0;" : "+l"(acc) : "l"(a), "l"(b));
}
__device__ __forceinline__ uint64_t pack2(float x) {
    uint64_t r;
    asm("mov.b64 %0, {%1, %1};" : "=l"(r) : "f"(x));
    return r;
}
__device__ __forceinline__ uint64_t pack2f(float x, float y) {
    uint64_t r;
    asm("mov.b64 %0, {%1, %2};" : "=l"(r) : "f"(x), "f"(y));
    return r;
}
__device__ __forceinline__ float2 unpack2(uint64_t v) {
    float2 r;
    asm("mov.b64 {%0, %1}, %2;" : "=f"(r.x), "=f"(r.y) : "l"(v));
    return r;
}

// ---------------- mean over L (partials only; final fold done in k_mse2) -----
__global__ void k_mean_part(const float* __restrict__ x) {
    int b = blockIdx.y, z = blockIdx.z;
    int c = blockIdx.x * 256 + threadIdx.x;
    const float* xb = x + (size_t)b * LL * CC + (size_t)z * (LL / LSPLIT) * CC + c;
    double acc = 0.0;
#pragma unroll 8
    for (int l = 0; l < LL / LSPLIT; l++) acc += (double)xb[(size_t)l * CC];
    g_part[((size_t)z * BB + b) * CC + c] = acc;
}

// ---------------- mse per token (recomputes mean from partials in smem) ------
__global__ void k_mse2(const float* __restrict__ x) {
    int l = blockIdx.x, b = blockIdx.y, t = threadIdx.x;
    __shared__ float smean[CC];
    for (int c = t; c < CC; c += 256) {
        double acc = 0.0;
#pragma unroll
        for (int z = 0; z < LSPLIT; z++) acc += g_part[((size_t)z * BB + b) * CC + c];
        smean[c] = (float)(acc / (double)LL);
    }
    __syncthreads();
    const float* row = x + ((size_t)b * LL + l) * CC;
    double acc = 0.0;
    for (int c = t; c < CC; c += 256) {
        float d = row[c] - smean[c];
        acc += (double)d * (double)d;
    }
    __shared__ double s[256];
    s[t] = acc;
    __syncthreads();
    for (int o = 128; o > 0; o >>= 1) {
        if (t < o) s[t] += s[t + o];
        __syncthreads();
    }
    if (t == 0) g_mse[b * LL + l] = (float)s[0];
}

// ---------------- top-1638 via bitonic sort + inverse map --------------------
__global__ void k_topk() {
    __shared__ float sv[LL];
    __shared__ int   si[LL];
    int b = blockIdx.x;
    for (int i = threadIdx.x; i < LL; i += blockDim.x) {
        sv[i] = g_mse[b * LL + i];
        si[i] = i;
    }
    __syncthreads();
    for (int k = 2; k <= LL; k <<= 1) {
        for (int j = k >> 1; j > 0; j >>= 1) {
            for (int i = threadIdx.x; i < LL; i += blockDim.x) {
                int ixj = i ^ j;
                if (ixj > i) {
                    float va = sv[i], vb = sv[ixj];
                    int   ia = si[i], ib = si[ixj];
                    bool a_before_b = (va > vb) || (va == vb && ia < ib);
                    bool up = ((i & k) == 0);
                    bool doswap = up ? (!a_before_b) : a_before_b;
                    if (doswap) {
                        sv[i] = vb; sv[ixj] = va;
                        si[i] = ib; si[ixj] = ia;
                    }
                }
            }
            __syncthreads();
        }
    }
    for (int i = threadIdx.x; i < LL; i += blockDim.x) g_minv[b * LL + i] = -1;
    __syncthreads();
    for (int i = threadIdx.x; i < MM; i += blockDim.x) {
        g_idx[b * MM + i] = si[i];
        g_minv[b * LL + si[i]] = i;
    }
}

// ---------------- bias concat + per-head scale (runs AFTER QKV gemm now) -----
__global__ void k_bias3(const float* __restrict__ qb, const float* __restrict__ vb,
                        const float* __restrict__ sml) {
    int n = blockIdx.x * 256 + threadIdx.x;
    if (n < C3) {
        float v = 0.f;
        if (n < CC) v = qb[n];
        else if (n >= 2 * CC) v = vb[n - 2 * CC];
        g_bias3[n] = v;
    }
    if (n < NHH) g_scl[n] = expf(fminf(sml[n], 4.6051702f));
}

// ---------------- fp32 GEMM with packed f32x2 FMA (R6 inner loop) ------------
// D[m][n] = sum_k A[m][k]*W[n][k] (+ bias[n] in mode 1)
// mode 0: A = x rows gathered by g_idx, W = W_qkv, out g_qkv, N=3072, NO bias
// mode 1: A = g_ao,                    W = W_proj, out g_po, N=1024, + biasin
__global__ void __launch_bounds__(256)
k_gemm2(int mode, const float* __restrict__ xin,
        const float* __restrict__ W, const float* __restrict__ biasin) {
    __shared__ float As[GKC * APAD];
    __shared__ float Bs[GKC * APAD];
    __shared__ int s_row[GTM];

    const float* A;
    float* Cout;
    int N;
    size_t aStr;
    if (mode == 0) {
        A = xin; Cout = g_qkv; N = C3; aStr = (size_t)LL * CC;
    } else {
        A = g_ao; Cout = g_po; N = CC; aStr = (size_t)MM * CC;
    }

    int b  = blockIdx.z;
    int n0 = blockIdx.x * GTN;
    int m0 = blockIdx.y * GTM;
    int tid = threadIdx.x;
    int tx = tid & 15, ty = tid >> 4;

    if (tid < GTM) {
        int m = m0 + tid;
        int src = 0;
        if (m < MM) src = (mode == 0) ? g_idx[b * MM + m] : m;
        s_row[tid] = src;
    }
    __syncthreads();

    const float* Ab = A + (size_t)b * aStr;

    // accumulators: 4 m-pairs x 8 n, packed along m
    uint64_t acc[4][8];
#pragma unroll
    for (int i = 0; i < 4; i++)
#pragma unroll
        for (int j = 0; j < 8; j++) acc[i][j] = 0ull;

    for (int k0 = 0; k0 < CC; k0 += GKC) {
        // load tiles: 128 rows x 32 k floats = 1024 float4 per matrix, 4/thread
#pragma unroll
        for (int i = 0; i < 4; i++) {
            int lin = tid + i * 256;
            int row = lin >> 3;
            int kq = (lin & 7) * 4;
            float4 va = __ldg((const float4*)(Ab + (size_t)s_row[row] * CC + k0 + kq));
            As[(kq + 0) * APAD + row] = va.x;
            As[(kq + 1) * APAD + row] = va.y;
            As[(kq + 2) * APAD + row] = va.z;
            As[(kq + 3) * APAD + row] = va.w;
            float4 vb = __ldg((const float4*)(W + (size_t)(n0 + row) * CC + k0 + kq));
            Bs[(kq + 0) * APAD + row] = vb.x;
            Bs[(kq + 1) * APAD + row] = vb.y;
            Bs[(kq + 2) * APAD + row] = vb.z;
            Bs[(kq + 3) * APAD + row] = vb.w;
        }
        __syncthreads();

#pragma unroll
        for (int kk = 0; kk < GKC; kk++) {
            ulonglong2 a01 = *(const ulonglong2*)&As[kk * APAD + ty * 8];
            ulonglong2 a23 = *(const ulonglong2*)&As[kk * APAD + ty * 8 + 4];
            float4 b0 = *(const float4*)&Bs[kk * APAD + tx * 8];
            float4 b1 = *(const float4*)&Bs[kk * APAD + tx * 8 + 4];
            uint64_t bp[8];
            bp[0] = pack2(b0.x); bp[1] = pack2(b0.y);
            bp[2] = pack2(b0.z); bp[3] = pack2(b0.w);
            bp[4] = pack2(b1.x); bp[5] = pack2(b1.y);
            bp[6] = pack2(b1.z); bp[7] = pack2(b1.w);
            uint64_t ap[4] = {a01.x, a01.y, a23.x, a23.y};
#pragma unroll
            for (int i = 0; i < 4; i++)
#pragma unroll
                for (int j = 0; j < 8; j++)
                    ffma2(acc[i][j], ap[i], bp[j]);
        }
        __syncthreads();
    }

    // epilogue: m pairs (ty*8 + 2*i, +1), n = tx*8 .. +7
    float* Cb = Cout + (size_t)b * MM * N;
    int nb = n0 + tx * 8;
    float bv[8];
#pragma unroll
    for (int j = 0; j < 8; j++) bv[j] = (mode == 1) ? biasin[nb + j] : 0.f;
#pragma unroll
    for (int i = 0; i < 4; i++) {
        int m = m0 + ty * 8 + i * 2;
        float2 r[8];
#pragma unroll
        for (int j = 0; j < 8; j++) r[j] = unpack2(acc[i][j]);
        if (m < MM) {
            float* d = Cb + (size_t)m * N + nb;
            *(float4*)d = make_float4(r[0].x + bv[0], r[1].x + bv[1], r[2].x + bv[2], r[3].x + bv[3]);
            *(float4*)(d + 4) = make_float4(r[4].x + bv[4], r[5].x + bv[5], r[6].x + bv[6], r[7].x + bv[7]);
        }
        if (m + 1 < MM) {
            float* d = Cb + (size_t)(m + 1) * N + nb;
            *(float4*)d = make_float4(r[0].y + bv[0], r[1].y + bv[1], r[2].y + bv[2], r[3].y + bv[3]);
            *(float4*)(d + 4) = make_float4(r[4].y + bv[4], r[5].y + bv[5], r[6].y + bv[6], r[7].y + bv[7]);
        }
    }
}

// ---------------- l2norm + scale + RoPE (adds q/v bias, moved from gemm) -----
__global__ void k_normrope(const float* __restrict__ rg, const float* __restrict__ qb,
                           const float* __restrict__ vb) {
    int bm = blockIdx.x;
    int b = bm / MM, m = bm % MM;
    int t = threadIdx.x;
    int g = t >> 4;
    int lane = t & 15;
    int lidx = g_idx[b * MM + m];
    const float* base = g_qkv + (size_t)bm * C3;

    float4 q4 = *(const float4*)(base + g * 64 + lane * 4);
    float4 k4 = *(const float4*)(base + CC + g * 64 + lane * 4);
    float4 v4 = *(const float4*)(base + 2 * CC + g * 64 + lane * 4);

    // add biases (K has none)
    float4 qbv = *(const float4*)(qb + g * 64 + lane * 4);
    float4 vbv = *(const float4*)(vb + g * 64 + lane * 4);
    q4.x += qbv.x; q4.y += qbv.y; q4.z += qbv.z; q4.w += qbv.w;
    v4.x += vbv.x; v4.y += vbv.y; v4.z += vbv.z; v4.w += vbv.w;

    float sq = q4.x * q4.x + q4.y * q4.y + q4.z * q4.z + q4.w * q4.w;
    float sk = k4.x * k4.x + k4.y * k4.y + k4.z * k4.z + k4.w * k4.w;
#pragma unroll
    for (int off = 8; off > 0; off >>= 1) {
        sq += __shfl_xor_sync(0xffffffffu, sq, off, 16);
        sk += __shfl_xor_sync(0xffffffffu, sk, off, 16);
    }
    float qs = g_scl[g] / fmaxf(sqrtf(sq), 1e-12f);
    float ks = 1.f / fmaxf(sqrtf(sk), 1e-12f);

    const float* cp = rg + (size_t)lidx * 32 + lane * 2;
    const float* sp = rg + (size_t)LL * 32 + (size_t)lidx * 32 + lane * 2;
    float c0 = cp[0], c1 = cp[1], s0 = sp[0], s1 = sp[1];

    float4 qo, ko;
    qo.x = (c0 * q4.x - s0 * q4.y) * qs;
    qo.y = (s0 * q4.x + c0 * q4.y) * qs;
    qo.z = (c1 * q4.z - s1 * q4.w) * qs;
    qo.w = (s1 * q4.z + c1 * q4.w) * qs;
    ko.x = (c0 * k4.x - s0 * k4.y) * ks;
    ko.y = (s0 * k4.x + c0 * k4.y) * ks;
    ko.z = (c1 * k4.z - s1 * k4.w) * ks;
    ko.w = (s1 * k4.z + c1 * k4.w) * ks;

    size_t hoff = (((size_t)(b * NHH + g)) * MM + m) * DHH + lane * 4;
    *(float4*)(g_q + hoff) = qo;
    *(float4*)(g_k + hoff) = ko;
    *(float4*)(g_v + hoff) = v4;
}

// ---------------- attention with packed f32x2 (R6 exact) ---------------------
// bounded-score softmax: |q.k| <= scale_mul -> subtract bound, no running max
__global__ void __launch_bounds__(64)
k_attn() {
    __shared__ float4 ks[64][16];
    __shared__ float4 vs[64][16];
    int bh = blockIdx.y;
    int q0 = blockIdx.x * 64;
    int t = threadIdx.x;
    int q = q0 + t;
    bool valid = q < MM;
    const float smax = g_scl[bh & (NHH - 1)];

    const float4* Q4 = (const float4*)(g_q + (size_t)bh * MM * DHH);
    const float4* K4 = (const float4*)(g_k + (size_t)bh * MM * DHH);
    const float4* V4 = (const float4*)(g_v + (size_t)bh * MM * DHH);

    uint64_t qr[32], o[32];
#pragma unroll
    for (int i = 0; i < 16; i++) {
        float4 v = valid ? Q4[(size_t)q * 16 + i] : make_float4(0, 0, 0, 0);
        qr[i * 2 + 0] = pack2f(v.x, v.y);
        qr[i * 2 + 1] = pack2f(v.z, v.w);
        o[i * 2 + 0] = 0ull;
        o[i * 2 + 1] = 0ull;
    }
    float lrun = 0.f;

    for (int k0 = 0; k0 < MM; k0 += 64) {
        int kn = min(64, MM - k0);
        for (int i = t; i < 64 * 16; i += 64) {
            int r = i >> 4, c2 = i & 15;
            if (k0 + r < MM) {
                ks[r][c2] = K4[(size_t)(k0 + r) * 16 + c2];
                vs[r][c2] = V4[(size_t)(k0 + r) * 16 + c2];
            }
        }
        __syncthreads();
        if (valid) {
            for (int kk = 0; kk < kn; kk++) {
                uint64_t s2 = 0ull;
                const ulonglong2* kp = (const ulonglong2*)&ks[kk][0];
#pragma unroll
                for (int i = 0; i < 16; i++) {
                    ulonglong2 kv = kp[i];
                    ffma2(s2, qr[i * 2 + 0], kv.x);
                    ffma2(s2, qr[i * 2 + 1], kv.y);
                }
                float2 sp2 = unpack2(s2);
                float p = __expf(sp2.x + sp2.y - smax);
                lrun += p;
                uint64_t p2 = pack2(p);
                const ulonglong2* vp = (const ulonglong2*)&vs[kk][0];
#pragma unroll
                for (int i = 0; i < 16; i++) {
                    ulonglong2 vv = vp[i];
                    ffma2(o[i * 2 + 0], p2, vv.x);
                    ffma2(o[i * 2 + 1], p2, vv.y);
                }
            }
        }
        __syncthreads();
    }

    if (valid) {
        float inv = 1.f / lrun;
        int b = bh >> 4, h = bh & 15;
        float4* out = (float4*)(g_ao + ((size_t)(b * MM + q)) * CC + h * DHH);
#pragma unroll
        for (int i = 0; i < 16; i++) {
            float2 e0 = unpack2(o[i * 2 + 0]);
            float2 e1 = unpack2(o[i * 2 + 1]);
            out[i] = make_float4(e0.x * inv, e0.y * inv, e1.x * inv, e1.y * inv);
        }
    }
}

// ---------------- fused output: x + (selected ? proj : upsample(cached)) -----
__global__ void k_out(const float* __restrict__ x, const float* __restrict__ cached,
                      float* __restrict__ out) {
    int l = blockIdx.x, b = blockIdx.y, t = threadIdx.x;
    int m = g_minv[b * LL + l];
    size_t xi = ((size_t)b * LL + l) * CC + t * 4;
    float4 xv = *(const float4*)(x + xi);
    float4 av;
    if (m >= 0) {
        av = *(const float4*)(g_po + ((size_t)b * MM + m) * CC + t * 4);
    } else {
        int hrow = l >> 6, wcol = l & 63;
        size_t ci = (((size_t)b * 32 + (hrow >> 1)) * 32 + (wcol >> 1)) * CC + t * 4;
        av = *(const float4*)(cached + ci);
    }
    *(float4*)(out + xi) = make_float4(xv.x + av.x, xv.y + av.y, xv.z + av.z, xv.w + av.w);
}

// ---------------- launch -----------------------------------------------------
extern "C" void kernel_launch(void* const* d_in, const int* in_sizes, int n_in,
                              void* d_out, int out_size) {
    (void)in_sizes; (void)n_in; (void)out_size;
    const float* x        = (const float*)d_in[0];
    const float* cached_x = (const float*)d_in[1];
    const float* W_qkv    = (const float*)d_in[2];
    const float* q_bias   = (const float*)d_in[3];
    const float* v_bias   = (const float*)d_in[4];
    const float* W_proj   = (const float*)d_in[5];
    const float* b_proj   = (const float*)d_in[6];
    const float* sml      = (const float*)d_in[7];
    const float* rope     = (const float*)d_in[8];
    float* out = (float*)d_out;

    // positions chosen so ncu's fixed capture slot (my 4th launch) = QKV GEMM
    k_mean_part<<<dim3(CC / 256, BB, LSPLIT), 256>>>(x);          // 1
    k_mse2<<<dim3(LL, BB), 256>>>(x);                             // 2
    k_topk<<<BB, 1024>>>();                                       // 3
    // QKV GEMM: M=1638 (gathered), N=3072, K=1024  (no bias here)
    k_gemm2<<<dim3(C3 / GTN, (MM + GTM - 1) / GTM, BB), 256>>>(0, x, W_qkv, (const float*)0); // 4
    k_bias3<<<C3 / 256, 256>>>(q_bias, v_bias, sml);              // 5
    k_normrope<<<BB * MM, 256>>>(rope, q_bias, v_bias);           // 6
    k_attn<<<dim3((MM + 63) / 64, BB * NHH), 64>>>();             // 7
    // proj GEMM: M=1638, N=1024, K=1024 (+ b_proj)
    k_gemm2<<<dim3(CC / GTN, (MM + GTM - 1) / GTM, BB), 256>>>(1, (const float*)0, W_proj, b_proj); // 8
    k_out<<<dim3(LL, BB), 256>>>(x, cached_x, out);               // 9
}

// round 13
// speedup vs baseline: 1.1098x; 1.1098x over previous
#include <cuda_runtime.h>
#include <math.h>
#include <stdint.h>

#define BB 2
#define LL 4096
#define CC 1024
#define NHH 16
#define DHH 64
#define MM 1638
#define C3 3072
#define LSPLIT 16

// GEMM tiling: 128x128 CTA tile, 32 k-step, 256 threads, 8x8 per thread
#define GTM 128
#define GTN 128
#define GKC 32
#define APAD 132   // smem pitch in floats (16B-aligned, reduces store conflicts)

// ---------------- scratch (device globals; no allocations allowed) ----------
__device__ double g_part[LSPLIT * BB * CC];
__device__ float  g_mean[BB * CC];
__device__ float  g_mse[BB * LL];
__device__ int    g_idx[BB * MM];
__device__ int    g_minv[BB * LL];
__device__ float  g_bias3[C3];
__device__ float  g_scl[NHH];
__device__ float  g_qkv[(size_t)BB * MM * C3];
__device__ float  g_q[(size_t)BB * NHH * MM * DHH];
__device__ float  g_k[(size_t)BB * NHH * MM * DHH];
__device__ float  g_v[(size_t)BB * NHH * MM * DHH];
__device__ float  g_ao[(size_t)BB * MM * CC];
__device__ float  g_po[(size_t)BB * MM * CC];

// ---------------- packed f32x2 helpers ---------------------------------------
__device__ __forceinline__ void ffma2(uint64_t& acc, uint64_t a, uint64_t b) {
    asm("fma.rn.f32x2 %0, %1, %2, %0;" : "+l"(acc) : "l"(a), "l"(b));
}
__device__ __forceinline__ uint64_t pack2(float x) {
    uint64_t r;
    asm("mov.b64 %0, {%1, %1};" : "=l"(r) : "f"(x));
    return r;
}
__device__ __forceinline__ uint64_t pack2f(float x, float y) {
    uint64_t r;
    asm("mov.b64 %0, {%1, %2};" : "=l"(r) : "f"(x), "f"(y));
    return r;
}
__device__ __forceinline__ float2 unpack2(uint64_t v) {
    float2 r;
    asm("mov.b64 {%0, %1}, %2;" : "=f"(r.x), "=f"(r.y) : "l"(v));
    return r;
}

// ---------------- mean over L -----------------------------------------------
__global__ void k_mean_part(const float* __restrict__ x) {
    int b = blockIdx.y, z = blockIdx.z;
    int c = blockIdx.x * 256 + threadIdx.x;
    const float* xb = x + (size_t)b * LL * CC + (size_t)z * (LL / LSPLIT) * CC + c;
    double acc = 0.0;
#pragma unroll 8
    for (int l = 0; l < LL / LSPLIT; l++) acc += (double)xb[(size_t)l * CC];
    g_part[((size_t)z * BB + b) * CC + c] = acc;
}

__global__ void k_mean_final() {
    int i = blockIdx.x * 256 + threadIdx.x;
    int b = i / CC, c = i % CC;
    double acc = 0.0;
#pragma unroll
    for (int z = 0; z < LSPLIT; z++) acc += g_part[((size_t)z * BB + b) * CC + c];
    g_mean[i] = (float)(acc / (double)LL);
}

// ---------------- mse per token ---------------------------------------------
__global__ void k_mse(const float* __restrict__ x) {
    int l = blockIdx.x, b = blockIdx.y, t = threadIdx.x;
    const float* row = x + ((size_t)b * LL + l) * CC;
    const float* mb  = g_mean + b * CC;
    double acc = 0.0;
    for (int c = t; c < CC; c += 256) {
        float d = row[c] - mb[c];
        acc += (double)d * (double)d;
    }
    __shared__ double s[256];
    s[t] = acc;
    __syncthreads();
    for (int o = 128; o > 0; o >>= 1) {
        if (t < o) s[t] += s[t + o];
        __syncthreads();
    }
    if (t == 0) g_mse[b * LL + l] = (float)s[0];
}

// ---------------- top-1638 via bitonic sort + inverse map --------------------
__global__ void k_topk() {
    __shared__ float sv[LL];
    __shared__ int   si[LL];
    int b = blockIdx.x;
    for (int i = threadIdx.x; i < LL; i += blockDim.x) {
        sv[i] = g_mse[b * LL + i];
        si[i] = i;
    }
    __syncthreads();
    for (int k = 2; k <= LL; k <<= 1) {
        for (int j = k >> 1; j > 0; j >>= 1) {
            for (int i = threadIdx.x; i < LL; i += blockDim.x) {
                int ixj = i ^ j;
                if (ixj > i) {
                    float va = sv[i], vb = sv[ixj];
                    int   ia = si[i], ib = si[ixj];
                    bool a_before_b = (va > vb) || (va == vb && ia < ib);
                    bool up = ((i & k) == 0);
                    bool doswap = up ? (!a_before_b) : a_before_b;
                    if (doswap) {
                        sv[i] = vb; sv[ixj] = va;
                        si[i] = ib; si[ixj] = ia;
                    }
                }
            }
            __syncthreads();
        }
    }
    for (int i = threadIdx.x; i < LL; i += blockDim.x) g_minv[b * LL + i] = -1;
    __syncthreads();
    for (int i = threadIdx.x; i < MM; i += blockDim.x) {
        g_idx[b * MM + i] = si[i];
        g_minv[b * LL + si[i]] = i;
    }
}

// ---------------- bias concat + per-head scale -------------------------------
__global__ void k_bias3(const float* __restrict__ qb, const float* __restrict__ vb,
                        const float* __restrict__ sml) {
    int n = blockIdx.x * 256 + threadIdx.x;
    if (n < C3) {
        float v = 0.f;
        if (n < CC) v = qb[n];
        else if (n >= 2 * CC) v = vb[n - 2 * CC];
        g_bias3[n] = v;
    }
    if (n < NHH) g_scl[n] = expf(fminf(sml[n], 4.6051702f));
}

// ---------------- fp32 GEMM with packed f32x2 FMA ----------------------------
// D[m][n] = sum_k A[m][k]*W[n][k] + bias[n]
// mode 0: A = x rows gathered by g_idx, W = W_qkv, out g_qkv, N=3072
// mode 1: A = g_ao,                    W = W_proj, out g_po, N=1024
// __launch_bounds__(256, 2): smem is 33.5KB -> 2 CTAs fit; cap regs so the RF
// fits 2 CTAs too (R12 profile: 126 regs -> 1 CTA/SM, occ 23.5%, issue 36%).
__global__ void __launch_bounds__(256, 2)
k_gemm2(int mode, const float* __restrict__ xin,
        const float* __restrict__ W, const float* __restrict__ biasin) {
    __shared__ float As[GKC * APAD];
    __shared__ float Bs[GKC * APAD];
    __shared__ int s_row[GTM];

    const float* A;
    const float* bias;
    float* Cout;
    int N;
    size_t aStr;
    if (mode == 0) {
        A = xin; bias = g_bias3; Cout = g_qkv; N = C3; aStr = (size_t)LL * CC;
    } else {
        A = g_ao; bias = biasin; Cout = g_po; N = CC; aStr = (size_t)MM * CC;
    }

    int b  = blockIdx.z;
    int n0 = blockIdx.x * GTN;
    int m0 = blockIdx.y * GTM;
    int tid = threadIdx.x;
    int tx = tid & 15, ty = tid >> 4;

    if (tid < GTM) {
        int m = m0 + tid;
        int src = 0;
        if (m < MM) src = (mode == 0) ? g_idx[b * MM + m] : m;
        s_row[tid] = src;
    }
    __syncthreads();

    const float* Ab = A + (size_t)b * aStr;

    // accumulators: 4 m-pairs x 8 n, packed along m
    uint64_t acc[4][8];
#pragma unroll
    for (int i = 0; i < 4; i++)
#pragma unroll
        for (int j = 0; j < 8; j++) acc[i][j] = 0ull;

    for (int k0 = 0; k0 < CC; k0 += GKC) {
        // load tiles: 128 rows x 32 k floats = 1024 float4 per matrix, 4/thread
#pragma unroll
        for (int i = 0; i < 4; i++) {
            int lin = tid + i * 256;
            int row = lin >> 3;
            int kq = (lin & 7) * 4;
            float4 va = __ldg((const float4*)(Ab + (size_t)s_row[row] * CC + k0 + kq));
            As[(kq + 0) * APAD + row] = va.x;
            As[(kq + 1) * APAD + row] = va.y;
            As[(kq + 2) * APAD + row] = va.z;
            As[(kq + 3) * APAD + row] = va.w;
            float4 vb = __ldg((const float4*)(W + (size_t)(n0 + row) * CC + k0 + kq));
            Bs[(kq + 0) * APAD + row] = vb.x;
            Bs[(kq + 1) * APAD + row] = vb.y;
            Bs[(kq + 2) * APAD + row] = vb.z;
            Bs[(kq + 3) * APAD + row] = vb.w;
        }
        __syncthreads();

#pragma unroll
        for (int kk = 0; kk < GKC; kk++) {
            ulonglong2 a01 = *(const ulonglong2*)&As[kk * APAD + ty * 8];
            ulonglong2 a23 = *(const ulonglong2*)&As[kk * APAD + ty * 8 + 4];
            float4 b0 = *(const float4*)&Bs[kk * APAD + tx * 8];
            float4 b1 = *(const float4*)&Bs[kk * APAD + tx * 8 + 4];
            uint64_t bp[8];
            bp[0] = pack2(b0.x); bp[1] = pack2(b0.y);
            bp[2] = pack2(b0.z); bp[3] = pack2(b0.w);
            bp[4] = pack2(b1.x); bp[5] = pack2(b1.y);
            bp[6] = pack2(b1.z); bp[7] = pack2(b1.w);
            uint64_t ap[4] = {a01.x, a01.y, a23.x, a23.y};
#pragma unroll
            for (int i = 0; i < 4; i++)
#pragma unroll
                for (int j = 0; j < 8; j++)
                    ffma2(acc[i][j], ap[i], bp[j]);
        }
        __syncthreads();
    }

    // epilogue: m pairs (ty*8 + 2*i, +1), n = tx*8 .. +7
    float* Cb = Cout + (size_t)b * MM * N;
    int nb = n0 + tx * 8;
    float bv[8];
#pragma unroll
    for (int j = 0; j < 8; j++) bv[j] = bias[nb + j];
#pragma unroll
    for (int i = 0; i < 4; i++) {
        int m = m0 + ty * 8 + i * 2;
        float2 r[8];
#pragma unroll
        for (int j = 0; j < 8; j++) r[j] = unpack2(acc[i][j]);
        if (m < MM) {
            float* d = Cb + (size_t)m * N + nb;
            *(float4*)d = make_float4(r[0].x + bv[0], r[1].x + bv[1], r[2].x + bv[2], r[3].x + bv[3]);
            *(float4*)(d + 4) = make_float4(r[4].x + bv[4], r[5].x + bv[5], r[6].x + bv[6], r[7].x + bv[7]);
        }
        if (m + 1 < MM) {
            float* d = Cb + (size_t)(m + 1) * N + nb;
            *(float4*)d = make_float4(r[0].y + bv[0], r[1].y + bv[1], r[2].y + bv[2], r[3].y + bv[3]);
            *(float4*)(d + 4) = make_float4(r[4].y + bv[4], r[5].y + bv[5], r[6].y + bv[6], r[7].y + bv[7]);
        }
    }
}

// ---------------- l2norm + scale + RoPE --------------------------------------
__global__ void k_normrope(const float* __restrict__ rg) {
    int bm = blockIdx.x;
    int b = bm / MM, m = bm % MM;
    int t = threadIdx.x;
    int g = t >> 4;
    int lane = t & 15;
    int lidx = g_idx[b * MM + m];
    const float* base = g_qkv + (size_t)bm * C3;

    float4 q4 = *(const float4*)(base + g * 64 + lane * 4);
    float4 k4 = *(const float4*)(base + CC + g * 64 + lane * 4);
    float4 v4 = *(const float4*)(base + 2 * CC + g * 64 + lane * 4);

    float sq = q4.x * q4.x + q4.y * q4.y + q4.z * q4.z + q4.w * q4.w;
    float sk = k4.x * k4.x + k4.y * k4.y + k4.z * k4.z + k4.w * k4.w;
#pragma unroll
    for (int off = 8; off > 0; off >>= 1) {
        sq += __shfl_xor_sync(0xffffffffu, sq, off, 16);
        sk += __shfl_xor_sync(0xffffffffu, sk, off, 16);
    }
    float qs = g_scl[g] / fmaxf(sqrtf(sq), 1e-12f);
    float ks = 1.f / fmaxf(sqrtf(sk), 1e-12f);

    const float* cp = rg + (size_t)lidx * 32 + lane * 2;
    const float* sp = rg + (size_t)LL * 32 + (size_t)lidx * 32 + lane * 2;
    float c0 = cp[0], c1 = cp[1], s0 = sp[0], s1 = sp[1];

    float4 qo, ko;
    qo.x = (c0 * q4.x - s0 * q4.y) * qs;
    qo.y = (s0 * q4.x + c0 * q4.y) * qs;
    qo.z = (c1 * q4.z - s1 * q4.w) * qs;
    qo.w = (s1 * q4.z + c1 * q4.w) * qs;
    ko.x = (c0 * k4.x - s0 * k4.y) * ks;
    ko.y = (s0 * k4.x + c0 * k4.y) * ks;
    ko.z = (c1 * k4.z - s1 * k4.w) * ks;
    ko.w = (s1 * k4.z + c1 * k4.w) * ks;

    size_t hoff = (((size_t)(b * NHH + g)) * MM + m) * DHH + lane * 4;
    *(float4*)(g_q + hoff) = qo;
    *(float4*)(g_k + hoff) = ko;
    *(float4*)(g_v + hoff) = v4;
}

// ---------------- attention with packed f32x2 --------------------------------
// bounded-score softmax: |q.k| <= scale_mul -> subtract bound, no running max
__global__ void __launch_bounds__(64)
k_attn() {
    __shared__ float4 ks[64][16];
    __shared__ float4 vs[64][16];
    int bh = blockIdx.y;
    int q0 = blockIdx.x * 64;
    int t = threadIdx.x;
    int q = q0 + t;
    bool valid = q < MM;
    const float smax = g_scl[bh & (NHH - 1)];

    const float4* Q4 = (const float4*)(g_q + (size_t)bh * MM * DHH);
    const float4* K4 = (const float4*)(g_k + (size_t)bh * MM * DHH);
    const float4* V4 = (const float4*)(g_v + (size_t)bh * MM * DHH);

    uint64_t qr[32], o[32];
#pragma unroll
    for (int i = 0; i < 16; i++) {
        float4 v = valid ? Q4[(size_t)q * 16 + i] : make_float4(0, 0, 0, 0);
        qr[i * 2 + 0] = pack2f(v.x, v.y);
        qr[i * 2 + 1] = pack2f(v.z, v.w);
        o[i * 2 + 0] = 0ull;
        o[i * 2 + 1] = 0ull;
    }
    float lrun = 0.f;

    for (int k0 = 0; k0 < MM; k0 += 64) {
        int kn = min(64, MM - k0);
        for (int i = t; i < 64 * 16; i += 64) {
            int r = i >> 4, c2 = i & 15;
            if (k0 + r < MM) {
                ks[r][c2] = K4[(size_t)(k0 + r) * 16 + c2];
                vs[r][c2] = V4[(size_t)(k0 + r) * 16 + c2];
            }
        }
        __syncthreads();
        if (valid) {
            for (int kk = 0; kk < kn; kk++) {
                uint64_t s2 = 0ull;
                const ulonglong2* kp = (const ulonglong2*)&ks[kk][0];
#pragma unroll
                for (int i = 0; i < 16; i++) {
                    ulonglong2 kv = kp[i];
                    ffma2(s2, qr[i * 2 + 0], kv.x);
                    ffma2(s2, qr[i * 2 + 1], kv.y);
                }
                float2 sp2 = unpack2(s2);
                float p = __expf(sp2.x + sp2.y - smax);
                lrun += p;
                uint64_t p2 = pack2(p);
                const ulonglong2* vp = (const ulonglong2*)&vs[kk][0];
#pragma unroll
                for (int i = 0; i < 16; i++) {
                    ulonglong2 vv = vp[i];
                    ffma2(o[i * 2 + 0], p2, vv.x);
                    ffma2(o[i * 2 + 1], p2, vv.y);
                }
            }
        }
        __syncthreads();
    }

    if (valid) {
        float inv = 1.f / lrun;
        int b = bh >> 4, h = bh & 15;
        float4* out = (float4*)(g_ao + ((size_t)(b * MM + q)) * CC + h * DHH);
#pragma unroll
        for (int i = 0; i < 16; i++) {
            float2 e0 = unpack2(o[i * 2 + 0]);
            float2 e1 = unpack2(o[i * 2 + 1]);
            out[i] = make_float4(e0.x * inv, e0.y * inv, e1.x * inv, e1.y * inv);
        }
    }
}

// ---------------- fused output: x + (selected ? proj : upsample(cached)) -----
__global__ void k_out(const float* __restrict__ x, const float* __restrict__ cached,
                      float* __restrict__ out) {
    int l = blockIdx.x, b = blockIdx.y, t = threadIdx.x;
    int m = g_minv[b * LL + l];
    size_t xi = ((size_t)b * LL + l) * CC + t * 4;
    float4 xv = *(const float4*)(x + xi);
    float4 av;
    if (m >= 0) {
        av = *(const float4*)(g_po + ((size_t)b * MM + m) * CC + t * 4);
    } else {
        int hrow = l >> 6, wcol = l & 63;
        size_t ci = (((size_t)b * 32 + (hrow >> 1)) * 32 + (wcol >> 1)) * CC + t * 4;
        av = *(const float4*)(cached + ci);
    }
    *(float4*)(out + xi) = make_float4(xv.x + av.x, xv.y + av.y, xv.z + av.z, xv.w + av.w);
}

// ---------------- launch -----------------------------------------------------
extern "C" void kernel_launch(void* const* d_in, const int* in_sizes, int n_in,
                              void* d_out, int out_size) {
    (void)in_sizes; (void)n_in; (void)out_size;
    const float* x        = (const float*)d_in[0];
    const float* cached_x = (const float*)d_in[1];
    const float* W_qkv    = (const float*)d_in[2];
    const float* q_bias   = (const float*)d_in[3];
    const float* v_bias   = (const float*)d_in[4];
    const float* W_proj   = (const float*)d_in[5];
    const float* b_proj   = (const float*)d_in[6];
    const float* sml      = (const float*)d_in[7];
    const float* rope     = (const float*)d_in[8];
    float* out = (float*)d_out;

    k_mean_part<<<dim3(CC / 256, BB, LSPLIT), 256>>>(x);
    k_mean_final<<<(BB * CC) / 256, 256>>>();
    k_mse<<<dim3(LL, BB), 256>>>(x);
    k_topk<<<BB, 1024>>>();
    k_bias3<<<C3 / 256, 256>>>(q_bias, v_bias, sml);

    // QKV GEMM: M=1638 (gathered), N=3072, K=1024
    k_gemm2<<<dim3(C3 / GTN, (MM + GTM - 1) / GTM, BB), 256>>>(0, x, W_qkv, (const float*)0);

    k_normrope<<<BB * MM, 256>>>(rope);
    k_attn<<<dim3((MM + 63) / 64, BB * NHH), 64>>>();

    // proj GEMM: M=1638, N=1024, K=1024
    k_gemm2<<<dim3(CC / GTN, (MM + GTM - 1) / GTM, BB), 256>>>(1, (const float*)0, W_proj, b_proj);

    k_out<<<dim3(LL, BB), 256>>>(x, cached_x, out);
}

// round 14
// speedup vs baseline: 1.2723x; 1.1464x over previous
#include <cuda_runtime.h>
#include <math.h>
#include <stdint.h>

#define BB 2
#define LL 4096
#define CC 1024
#define NHH 16
#define DHH 64
#define MM 1638
#define C3 3072
#define LSPLIT 16

// GEMM tiling: 128(m) x 64(n) CTA tile, 32 k-step, 256 threads, 8x4 per thread
#define GTM 128
#define GTN 64
#define GKC 32
#define APAD 132   // A smem pitch in floats
#define BPAD 68    // B smem pitch in floats

// ---------------- scratch (device globals; no allocations allowed) ----------
__device__ double g_part[LSPLIT * BB * CC];
__device__ float  g_mean[BB * CC];
__device__ float  g_mse[BB * LL];
__device__ int    g_idx[BB * MM];
__device__ int    g_minv[BB * LL];
__device__ float  g_bias3[C3];
__device__ float  g_scl[NHH];
__device__ float  g_qkv[(size_t)BB * MM * C3];
__device__ float  g_q[(size_t)BB * NHH * MM * DHH];
__device__ float  g_k[(size_t)BB * NHH * MM * DHH];
__device__ float  g_v[(size_t)BB * NHH * MM * DHH];
__device__ float  g_ao[(size_t)BB * MM * CC];
__device__ float  g_po[(size_t)BB * MM * CC];

// ---------------- packed f32x2 helpers ---------------------------------------
__device__ __forceinline__ void ffma2(uint64_t& acc, uint64_t a, uint64_t b) {
    asm("fma.rn.f32x2 %0, %1, %2, %0;" : "+l"(acc) : "l"(a), "l"(b));
}
__device__ __forceinline__ uint64_t pack2(float x) {
    uint64_t r;
    asm("mov.b64 %0, {%1, %1};" : "=l"(r) : "f"(x));
    return r;
}
__device__ __forceinline__ uint64_t pack2f(float x, float y) {
    uint64_t r;
    asm("mov.b64 %0, {%1, %2};" : "=l"(r) : "f"(x), "f"(y));
    return r;
}
__device__ __forceinline__ float2 unpack2(uint64_t v) {
    float2 r;
    asm("mov.b64 {%0, %1}, %2;" : "=f"(r.x), "=f"(r.y) : "l"(v));
    return r;
}

// ---------------- mean over L -----------------------------------------------
__global__ void k_mean_part(const float* __restrict__ x) {
    int b = blockIdx.y, z = blockIdx.z;
    int c = blockIdx.x * 256 + threadIdx.x;
    const float* xb = x + (size_t)b * LL * CC + (size_t)z * (LL / LSPLIT) * CC + c;
    double acc = 0.0;
#pragma unroll 8
    for (int l = 0; l < LL / LSPLIT; l++) acc += (double)xb[(size_t)l * CC];
    g_part[((size_t)z * BB + b) * CC + c] = acc;
}

__global__ void k_mean_final() {
    int i = blockIdx.x * 256 + threadIdx.x;
    int b = i / CC, c = i % CC;
    double acc = 0.0;
#pragma unroll
    for (int z = 0; z < LSPLIT; z++) acc += g_part[((size_t)z * BB + b) * CC + c];
    g_mean[i] = (float)(acc / (double)LL);
}

// ---------------- mse per token ---------------------------------------------
__global__ void k_mse(const float* __restrict__ x) {
    int l = blockIdx.x, b = blockIdx.y, t = threadIdx.x;
    const float* row = x + ((size_t)b * LL + l) * CC;
    const float* mb  = g_mean + b * CC;
    double acc = 0.0;
    for (int c = t; c < CC; c += 256) {
        float d = row[c] - mb[c];
        acc += (double)d * (double)d;
    }
    __shared__ double s[256];
    s[t] = acc;
    __syncthreads();
    for (int o = 128; o > 0; o >>= 1) {
        if (t < o) s[t] += s[t + o];
        __syncthreads();
    }
    if (t == 0) g_mse[b * LL + l] = (float)s[0];
}

// ---------------- top-1638 via bitonic sort + inverse map --------------------
__global__ void k_topk() {
    __shared__ float sv[LL];
    __shared__ int   si[LL];
    int b = blockIdx.x;
    for (int i = threadIdx.x; i < LL; i += blockDim.x) {
        sv[i] = g_mse[b * LL + i];
        si[i] = i;
    }
    __syncthreads();
    for (int k = 2; k <= LL; k <<= 1) {
        for (int j = k >> 1; j > 0; j >>= 1) {
            for (int i = threadIdx.x; i < LL; i += blockDim.x) {
                int ixj = i ^ j;
                if (ixj > i) {
                    float va = sv[i], vb = sv[ixj];
                    int   ia = si[i], ib = si[ixj];
                    bool a_before_b = (va > vb) || (va == vb && ia < ib);
                    bool up = ((i & k) == 0);
                    bool doswap = up ? (!a_before_b) : a_before_b;
                    if (doswap) {
                        sv[i] = vb; sv[ixj] = va;
                        si[i] = ib; si[ixj] = ia;
                    }
                }
            }
            __syncthreads();
        }
    }
    for (int i = threadIdx.x; i < LL; i += blockDim.x) g_minv[b * LL + i] = -1;
    __syncthreads();
    for (int i = threadIdx.x; i < MM; i += blockDim.x) {
        g_idx[b * MM + i] = si[i];
        g_minv[b * LL + si[i]] = i;
    }
}

// ---------------- bias concat + per-head scale -------------------------------
__global__ void k_bias3(const float* __restrict__ qb, const float* __restrict__ vb,
                        const float* __restrict__ sml) {
    int n = blockIdx.x * 256 + threadIdx.x;
    if (n < C3) {
        float v = 0.f;
        if (n < CC) v = qb[n];
        else if (n >= 2 * CC) v = vb[n - 2 * CC];
        g_bias3[n] = v;
    }
    if (n < NHH) g_scl[n] = expf(fminf(sml[n], 4.6051702f));
}

// ---------------- fp32 GEMM, 128x64 tile, packed f32x2 FMA -------------------
// Thread tile 8(m)x4(n): 16 u64 accumulators -> ~80 regs -> 3 CTAs/SM.
// mode 0: A = x rows gathered by g_idx, W = W_qkv, out g_qkv, N=3072
// mode 1: A = g_ao,                    W = W_proj, out g_po, N=1024
__global__ void __launch_bounds__(256)
k_gemm2(int mode, const float* __restrict__ xin,
        const float* __restrict__ W, const float* __restrict__ biasin) {
    __shared__ float As[GKC * APAD];
    __shared__ float Bs[GKC * BPAD];
    __shared__ int s_row[GTM];

    const float* A;
    const float* bias;
    float* Cout;
    int N;
    size_t aStr;
    if (mode == 0) {
        A = xin; bias = g_bias3; Cout = g_qkv; N = C3; aStr = (size_t)LL * CC;
    } else {
        A = g_ao; bias = biasin; Cout = g_po; N = CC; aStr = (size_t)MM * CC;
    }

    int b  = blockIdx.z;
    int n0 = blockIdx.x * GTN;
    int m0 = blockIdx.y * GTM;
    int tid = threadIdx.x;
    int tx = tid & 15, ty = tid >> 4;   // tx: n (4 each), ty: m (8 each)

    if (tid < GTM) {
        int m = m0 + tid;
        int src = 0;
        if (m < MM) src = (mode == 0) ? g_idx[b * MM + m] : m;
        s_row[tid] = src;
    }
    __syncthreads();

    const float* Ab = A + (size_t)b * aStr;

    // accumulators: 4 m-pairs x 4 n, packed along m
    uint64_t acc[4][4];
#pragma unroll
    for (int i = 0; i < 4; i++)
#pragma unroll
        for (int j = 0; j < 4; j++) acc[i][j] = 0ull;

    for (int k0 = 0; k0 < CC; k0 += GKC) {
        // A tile: 128 rows x 32 k = 1024 float4, 4 per thread
#pragma unroll
        for (int i = 0; i < 4; i++) {
            int lin = tid + i * 256;
            int row = lin >> 3;
            int kq = (lin & 7) * 4;
            float4 va = __ldg((const float4*)(Ab + (size_t)s_row[row] * CC + k0 + kq));
            As[(kq + 0) * APAD + row] = va.x;
            As[(kq + 1) * APAD + row] = va.y;
            As[(kq + 2) * APAD + row] = va.z;
            As[(kq + 3) * APAD + row] = va.w;
        }
        // B tile: 64 rows x 32 k = 512 float4, 2 per thread
#pragma unroll
        for (int i = 0; i < 2; i++) {
            int lin = tid + i * 256;
            int row = lin >> 3;
            int kq = (lin & 7) * 4;
            float4 vb = __ldg((const float4*)(W + (size_t)(n0 + row) * CC + k0 + kq));
            Bs[(kq + 0) * BPAD + row] = vb.x;
            Bs[(kq + 1) * BPAD + row] = vb.y;
            Bs[(kq + 2) * BPAD + row] = vb.z;
            Bs[(kq + 3) * BPAD + row] = vb.w;
        }
        __syncthreads();

#pragma unroll
        for (int kk = 0; kk < GKC; kk++) {
            ulonglong2 a01 = *(const ulonglong2*)&As[kk * APAD + ty * 8];
            ulonglong2 a23 = *(const ulonglong2*)&As[kk * APAD + ty * 8 + 4];
            float4 b0 = *(const float4*)&Bs[kk * BPAD + tx * 4];
            uint64_t bp[4];
            bp[0] = pack2(b0.x); bp[1] = pack2(b0.y);
            bp[2] = pack2(b0.z); bp[3] = pack2(b0.w);
            uint64_t ap[4] = {a01.x, a01.y, a23.x, a23.y};
#pragma unroll
            for (int i = 0; i < 4; i++)
#pragma unroll
                for (int j = 0; j < 4; j++)
                    ffma2(acc[i][j], ap[i], bp[j]);
        }
        __syncthreads();
    }

    // epilogue: m pairs (ty*8 + 2*i, +1), n = tx*4 .. +3
    float* Cb = Cout + (size_t)b * MM * N;
    int nb = n0 + tx * 4;
    float4 bv = *(const float4*)(bias + nb);
#pragma unroll
    for (int i = 0; i < 4; i++) {
        int m = m0 + ty * 8 + i * 2;
        float2 r[4];
#pragma unroll
        for (int j = 0; j < 4; j++) r[j] = unpack2(acc[i][j]);
        if (m < MM) {
            *(float4*)(Cb + (size_t)m * N + nb) =
                make_float4(r[0].x + bv.x, r[1].x + bv.y, r[2].x + bv.z, r[3].x + bv.w);
        }
        if (m + 1 < MM) {
            *(float4*)(Cb + (size_t)(m + 1) * N + nb) =
                make_float4(r[0].y + bv.x, r[1].y + bv.y, r[2].y + bv.z, r[3].y + bv.w);
        }
    }
}

// ---------------- l2norm + scale + RoPE --------------------------------------
__global__ void k_normrope(const float* __restrict__ rg) {
    int bm = blockIdx.x;
    int b = bm / MM, m = bm % MM;
    int t = threadIdx.x;
    int g = t >> 4;
    int lane = t & 15;
    int lidx = g_idx[b * MM + m];
    const float* base = g_qkv + (size_t)bm * C3;

    float4 q4 = *(const float4*)(base + g * 64 + lane * 4);
    float4 k4 = *(const float4*)(base + CC + g * 64 + lane * 4);
    float4 v4 = *(const float4*)(base + 2 * CC + g * 64 + lane * 4);

    float sq = q4.x * q4.x + q4.y * q4.y + q4.z * q4.z + q4.w * q4.w;
    float sk = k4.x * k4.x + k4.y * k4.y + k4.z * k4.z + k4.w * k4.w;
#pragma unroll
    for (int off = 8; off > 0; off >>= 1) {
        sq += __shfl_xor_sync(0xffffffffu, sq, off, 16);
        sk += __shfl_xor_sync(0xffffffffu, sk, off, 16);
    }
    float qs = g_scl[g] / fmaxf(sqrtf(sq), 1e-12f);
    float ks = 1.f / fmaxf(sqrtf(sk), 1e-12f);

    const float* cp = rg + (size_t)lidx * 32 + lane * 2;
    const float* sp = rg + (size_t)LL * 32 + (size_t)lidx * 32 + lane * 2;
    float c0 = cp[0], c1 = cp[1], s0 = sp[0], s1 = sp[1];

    float4 qo, ko;
    qo.x = (c0 * q4.x - s0 * q4.y) * qs;
    qo.y = (s0 * q4.x + c0 * q4.y) * qs;
    qo.z = (c1 * q4.z - s1 * q4.w) * qs;
    qo.w = (s1 * q4.z + c1 * q4.w) * qs;
    ko.x = (c0 * k4.x - s0 * k4.y) * ks;
    ko.y = (s0 * k4.x + c0 * k4.y) * ks;
    ko.z = (c1 * k4.z - s1 * k4.w) * ks;
    ko.w = (s1 * k4.z + c1 * k4.w) * ks;

    size_t hoff = (((size_t)(b * NHH + g)) * MM + m) * DHH + lane * 4;
    *(float4*)(g_q + hoff) = qo;
    *(float4*)(g_k + hoff) = ko;
    *(float4*)(g_v + hoff) = v4;
}

// ---------------- attention with packed f32x2 --------------------------------
// bounded-score softmax: |q.k| <= scale_mul -> subtract bound, no running max
__global__ void __launch_bounds__(64)
k_attn() {
    __shared__ float4 ks[64][16];
    __shared__ float4 vs[64][16];
    int bh = blockIdx.y;
    int q0 = blockIdx.x * 64;
    int t = threadIdx.x;
    int q = q0 + t;
    bool valid = q < MM;
    const float smax = g_scl[bh & (NHH - 1)];

    const float4* Q4 = (const float4*)(g_q + (size_t)bh * MM * DHH);
    const float4* K4 = (const float4*)(g_k + (size_t)bh * MM * DHH);
    const float4* V4 = (const float4*)(g_v + (size_t)bh * MM * DHH);

    uint64_t qr[32], o[32];
#pragma unroll
    for (int i = 0; i < 16; i++) {
        float4 v = valid ? Q4[(size_t)q * 16 + i] : make_float4(0, 0, 0, 0);
        qr[i * 2 + 0] = pack2f(v.x, v.y);
        qr[i * 2 + 1] = pack2f(v.z, v.w);
        o[i * 2 + 0] = 0ull;
        o[i * 2 + 1] = 0ull;
    }
    float lrun = 0.f;

    for (int k0 = 0; k0 < MM; k0 += 64) {
        int kn = min(64, MM - k0);
        for (int i = t; i < 64 * 16; i += 64) {
            int r = i >> 4, c2 = i & 15;
            if (k0 + r < MM) {
                ks[r][c2] = K4[(size_t)(k0 + r) * 16 + c2];
                vs[r][c2] = V4[(size_t)(k0 + r) * 16 + c2];
            }
        }
        __syncthreads();
        if (valid) {
            for (int kk = 0; kk < kn; kk++) {
                uint64_t s2 = 0ull;
                const ulonglong2* kp = (const ulonglong2*)&ks[kk][0];
#pragma unroll
                for (int i = 0; i < 16; i++) {
                    ulonglong2 kv = kp[i];
                    ffma2(s2, qr[i * 2 + 0], kv.x);
                    ffma2(s2, qr[i * 2 + 1], kv.y);
                }
                float2 sp2 = unpack2(s2);
                float p = __expf(sp2.x + sp2.y - smax);
                lrun += p;
                uint64_t p2 = pack2(p);
                const ulonglong2* vp = (const ulonglong2*)&vs[kk][0];
#pragma unroll
                for (int i = 0; i < 16; i++) {
                    ulonglong2 vv = vp[i];
                    ffma2(o[i * 2 + 0], p2, vv.x);
                    ffma2(o[i * 2 + 1], p2, vv.y);
                }
            }
        }
        __syncthreads();
    }

    if (valid) {
        float inv = 1.f / lrun;
        int b = bh >> 4, h = bh & 15;
        float4* out = (float4*)(g_ao + ((size_t)(b * MM + q)) * CC + h * DHH);
#pragma unroll
        for (int i = 0; i < 16; i++) {
            float2 e0 = unpack2(o[i * 2 + 0]);
            float2 e1 = unpack2(o[i * 2 + 1]);
            out[i] = make_float4(e0.x * inv, e0.y * inv, e1.x * inv, e1.y * inv);
        }
    }
}

// ---------------- fused output: x + (selected ? proj : upsample(cached)) -----
__global__ void k_out(const float* __restrict__ x, const float* __restrict__ cached,
                      float* __restrict__ out) {
    int l = blockIdx.x, b = blockIdx.y, t = threadIdx.x;
    int m = g_minv[b * LL + l];
    size_t xi = ((size_t)b * LL + l) * CC + t * 4;
    float4 xv = *(const float4*)(x + xi);
    float4 av;
    if (m >= 0) {
        av = *(const float4*)(g_po + ((size_t)b * MM + m) * CC + t * 4);
    } else {
        int hrow = l >> 6, wcol = l & 63;
        size_t ci = (((size_t)b * 32 + (hrow >> 1)) * 32 + (wcol >> 1)) * CC + t * 4;
        av = *(const float4*)(cached + ci);
    }
    *(float4*)(out + xi) = make_float4(xv.x + av.x, xv.y + av.y, xv.z + av.z, xv.w + av.w);
}

// ---------------- launch -----------------------------------------------------
extern "C" void kernel_launch(void* const* d_in, const int* in_sizes, int n_in,
                              void* d_out, int out_size) {
    (void)in_sizes; (void)n_in; (void)out_size;
    const float* x        = (const float*)d_in[0];
    const float* cached_x = (const float*)d_in[1];
    const float* W_qkv    = (const float*)d_in[2];
    const float* q_bias   = (const float*)d_in[3];
    const float* v_bias   = (const float*)d_in[4];
    const float* W_proj   = (const float*)d_in[5];
    const float* b_proj   = (const float*)d_in[6];
    const float* sml      = (const float*)d_in[7];
    const float* rope     = (const float*)d_in[8];
    float* out = (float*)d_out;

    k_mean_part<<<dim3(CC / 256, BB, LSPLIT), 256>>>(x);
    k_mean_final<<<(BB * CC) / 256, 256>>>();
    k_mse<<<dim3(LL, BB), 256>>>(x);
    k_topk<<<BB, 1024>>>();
    k_bias3<<<C3 / 256, 256>>>(q_bias, v_bias, sml);

    // QKV GEMM: M=1638 (gathered), N=3072, K=1024
    k_gemm2<<<dim3(C3 / GTN, (MM + GTM - 1) / GTM, BB), 256>>>(0, x, W_qkv, (const float*)0);

    k_normrope<<<BB * MM, 256>>>(rope);
    k_attn<<<dim3((MM + 63) / 64, BB * NHH), 64>>>();

    // proj GEMM: M=1638, N=1024, K=1024
    k_gemm2<<<dim3(CC / GTN, (MM + GTM - 1) / GTM, BB), 256>>>(1, (const float*)0, W_proj, b_proj);

    k_out<<<dim3(LL, BB), 256>>>(x, cached_x, out);
}